// round 2
// baseline (speedup 1.0000x reference)
#include <cuda_runtime.h>
#include <math.h>

#define BB     2
#define SS     4096
#define DD     1024
#define HH     16
#define DH     64
#define SEGLEN 512
#define PP     16
#define NWIN   8
#define INNER  1024
#define NTOK   (BB * SS)   // 8192

// Scratch (device globals — allocation inside kernel_launch is forbidden)
__device__ float g_h[NTOK * DD];                 // 32 MB  rmsnorm output
__device__ float g_qkv[NTOK * 3 * INNER];        // 96 MB  qkv projection
__device__ float g_attn[NTOK * INNER];           // 32 MB  attention output (token-major)

// ---------------------------------------------------------------------------
// Kernel 1: RMSNorm. One block per token row of 1024 floats.
// ---------------------------------------------------------------------------
__global__ __launch_bounds__(256) void rmsnorm_k(const float* __restrict__ x,
                                                 const float* __restrict__ gamma,
                                                 float* __restrict__ h) {
    int row = blockIdx.x;
    int t = threadIdx.x;
    const float4* xr = reinterpret_cast<const float4*>(x + (size_t)row * DD);
    const float4* gr = reinterpret_cast<const float4*>(gamma);

    float4 v = xr[t];
    float ss = v.x * v.x + v.y * v.y + v.z * v.z + v.w * v.w;
    #pragma unroll
    for (int o = 16; o > 0; o >>= 1) ss += __shfl_xor_sync(0xffffffffu, ss, o);

    __shared__ float red[8];
    int warp = t >> 5, lane = t & 31;
    if (lane == 0) red[warp] = ss;
    __syncthreads();
    if (warp == 0) {
        float s2 = (lane < 8) ? red[lane] : 0.0f;
        #pragma unroll
        for (int o = 16; o > 0; o >>= 1) s2 += __shfl_xor_sync(0xffffffffu, s2, o);
        if (lane == 0) red[0] = s2;
    }
    __syncthreads();

    float inv = rsqrtf(red[0] * (1.0f / DD) + 1e-6f);
    float4 g = gr[t];
    float4 o4;
    o4.x = v.x * inv * g.x;
    o4.y = v.y * inv * g.y;
    o4.z = v.z * inv * g.z;
    o4.w = v.w * inv * g.w;
    reinterpret_cast<float4*>(h + (size_t)row * DD)[t] = o4;
}

// ---------------------------------------------------------------------------
// Kernel 2/4: SGEMM  C[M,N] = A[M,K] @ B[K,N], all row-major fp32.
// 64x64 block tile, BK=16, 256 threads, 4x4 microtile. Assumes M,N%64==0, K%16==0.
// ---------------------------------------------------------------------------
#define GBM 64
#define GBN 64
#define GBK 16

__global__ __launch_bounds__(256) void sgemm_k(const float* __restrict__ A,
                                               const float* __restrict__ B,
                                               float* __restrict__ C,
                                               int M, int N, int K) {
    __shared__ __align__(16) float As[GBK][GBM + 4];   // stored transposed: As[k][m]
    __shared__ __align__(16) float Bs[GBK][GBN + 4];

    int tid = threadIdx.x;
    int tx = tid & 15, ty = tid >> 4;
    int m0 = blockIdx.y * GBM, n0 = blockIdx.x * GBN;

    int arow = tid >> 2;            // 0..63 (m within tile)
    int acol = (tid & 3) * 4;       // k offset 0,4,8,12
    int brow = tid >> 4;            // 0..15 (k within tile)
    int bcol = (tid & 15) * 4;      // n offset

    float acc[4][4] = {};

    for (int k0 = 0; k0 < K; k0 += GBK) {
        float4 a = *reinterpret_cast<const float4*>(&A[(size_t)(m0 + arow) * K + k0 + acol]);
        As[acol + 0][arow] = a.x;
        As[acol + 1][arow] = a.y;
        As[acol + 2][arow] = a.z;
        As[acol + 3][arow] = a.w;
        float4 b = *reinterpret_cast<const float4*>(&B[(size_t)(k0 + brow) * N + n0 + bcol]);
        *reinterpret_cast<float4*>(&Bs[brow][bcol]) = b;
        __syncthreads();

        #pragma unroll
        for (int kk = 0; kk < GBK; kk++) {
            float4 av = *reinterpret_cast<const float4*>(&As[kk][ty * 4]);
            float4 bv = *reinterpret_cast<const float4*>(&Bs[kk][tx * 4]);
            float ar[4] = {av.x, av.y, av.z, av.w};
            float br[4] = {bv.x, bv.y, bv.z, bv.w};
            #pragma unroll
            for (int i2 = 0; i2 < 4; i2++)
                #pragma unroll
                for (int j2 = 0; j2 < 4; j2++)
                    acc[i2][j2] += ar[i2] * br[j2];
        }
        __syncthreads();
    }

    #pragma unroll
    for (int i2 = 0; i2 < 4; i2++) {
        float4 o4 = make_float4(acc[i2][0], acc[i2][1], acc[i2][2], acc[i2][3]);
        *reinterpret_cast<float4*>(&C[(size_t)(m0 + ty * 4 + i2) * N + n0 + tx * 4]) = o4;
    }
}

// ---------------------------------------------------------------------------
// Kernel 3: windowed attention with persistent memory tokens.
// Block = (q-tile of 128, window*head, batch). One query row per thread.
// K/V chunks of 32 keys staged in smem; online softmax; causal chunk skip.
// Key index j in [0,528): j<16 -> memory token (always attended),
// j>=16 -> segment token j-16, attended iff j <= i+16.
// ---------------------------------------------------------------------------
__global__ __launch_bounds__(128) void attn_k(const float* __restrict__ qkv,
                                              const float* __restrict__ pmk,
                                              const float* __restrict__ pmv,
                                              float* __restrict__ out) {
    int qt = blockIdx.x;             // 0..3 query tiles of 128
    int wh = blockIdx.y;             // 0..NWIN*HH-1
    int b  = blockIdx.z;
    int w = wh >> 4;                 // window
    int h = wh & 15;                 // head
    int t = threadIdx.x;
    int i = qt * 128 + t;            // query position within segment
    size_t tok = (size_t)(b * SS + w * SEGLEN + i);

    __shared__ float4 Ks[32][16];
    __shared__ float4 Vs[32][16];

    const float sc = 0.125f;         // 1/sqrt(64)
    float4 q4[16];
    const float4* qp = reinterpret_cast<const float4*>(qkv + tok * 3072 + h * 64);
    #pragma unroll
    for (int r = 0; r < 16; r++) {
        float4 v = qp[r];
        q4[r] = make_float4(v.x * sc, v.y * sc, v.z * sc, v.w * sc);
    }

    float m = -INFINITY, l = 0.0f;
    float4 acc[16];
    #pragma unroll
    for (int r = 0; r < 16; r++) acc[r] = make_float4(0.f, 0.f, 0.f, 0.f);

    const int total = SEGLEN + PP;                       // 528
    int kmax = min(total - 1, qt * 128 + 127 + PP);      // last key any thread in tile needs
    int nch = (kmax >> 5) + 1;

    for (int c = 0; c < nch; c++) {
        int c0 = c * 32;
        int nk = min(32, total - c0);

        // cooperative K/V load: 128 threads x 4 float4s
        #pragma unroll
        for (int r = 0; r < 4; r++) {
            int idx = t + 128 * r;
            int j = idx >> 4;
            int f = idx & 15;
            if (j < nk) {
                int gj = c0 + j;
                const float4 *kp, *vp;
                if (gj < PP) {
                    kp = reinterpret_cast<const float4*>(pmk + (h * PP + gj) * 64);
                    vp = reinterpret_cast<const float4*>(pmv + (h * PP + gj) * 64);
                } else {
                    size_t ktok = (size_t)(b * SS + w * SEGLEN + (gj - PP));
                    kp = reinterpret_cast<const float4*>(qkv + ktok * 3072 + 1024 + h * 64);
                    vp = reinterpret_cast<const float4*>(qkv + ktok * 3072 + 2048 + h * 64);
                }
                Ks[j][f] = kp[f];
                Vs[j][f] = vp[f];
            }
        }
        __syncthreads();

        int jv = min(nk - 1, i + PP - c0);   // last valid key within chunk for this query
        float s[32];
        float smax = -INFINITY;
        #pragma unroll
        for (int j = 0; j < 32; j++) {
            if (j <= jv) {
                float d = 0.0f;
                #pragma unroll
                for (int r = 0; r < 16; r++) {
                    float4 kk = Ks[j][r];
                    d += q4[r].x * kk.x + q4[r].y * kk.y + q4[r].z * kk.z + q4[r].w * kk.w;
                }
                s[j] = d;
                smax = fmaxf(smax, d);
            } else {
                s[j] = -INFINITY;
            }
        }

        if (jv >= 0) {
            float newm = fmaxf(m, smax);
            float corr = __expf(m - newm);   // m=-inf only before first chunk; chunk 0 always valid
            l *= corr;
            #pragma unroll
            for (int r = 0; r < 16; r++) {
                acc[r].x *= corr; acc[r].y *= corr;
                acc[r].z *= corr; acc[r].w *= corr;
            }
            m = newm;
            #pragma unroll
            for (int j = 0; j < 32; j++) {
                if (j <= jv) {
                    float p = __expf(s[j] - m);
                    l += p;
                    #pragma unroll
                    for (int r = 0; r < 16; r++) {
                        float4 vv = Vs[j][r];
                        acc[r].x += p * vv.x; acc[r].y += p * vv.y;
                        acc[r].z += p * vv.z; acc[r].w += p * vv.w;
                    }
                }
            }
        }
        __syncthreads();
    }

    float invl = 1.0f / l;
    float4* op = reinterpret_cast<float4*>(out + tok * 1024 + h * 64);
    #pragma unroll
    for (int r = 0; r < 16; r++)
        op[r] = make_float4(acc[r].x * invl, acc[r].y * invl,
                            acc[r].z * invl, acc[r].w * invl);
}

// ---------------------------------------------------------------------------
extern "C" void kernel_launch(void* const* d_in, const int* in_sizes, int n_in,
                              void* d_out, int out_size) {
    const float* x     = (const float*)d_in[0];
    const float* gamma = (const float*)d_in[1];
    const float* w_qkv = (const float*)d_in[2];
    const float* w_out = (const float*)d_in[3];
    const float* pm_k  = (const float*)d_in[4];
    const float* pm_v  = (const float*)d_in[5];
    float* out = (float*)d_out;

    float *hbuf, *qkvbuf, *abuf;
    cudaGetSymbolAddress((void**)&hbuf,   g_h);
    cudaGetSymbolAddress((void**)&qkvbuf, g_qkv);
    cudaGetSymbolAddress((void**)&abuf,   g_attn);

    // 1) RMSNorm
    rmsnorm_k<<<NTOK, 256>>>(x, gamma, hbuf);

    // 2) QKV projection: (8192 x 1024) @ (1024 x 3072)
    sgemm_k<<<dim3(3 * INNER / GBN, NTOK / GBM), 256>>>(hbuf, w_qkv, qkvbuf,
                                                        NTOK, 3 * INNER, DD);

    // 3) Attention
    attn_k<<<dim3(SEGLEN / 128, NWIN * HH, BB), 128>>>(qkvbuf, pm_k, pm_v, abuf);

    // 4) Output projection: (8192 x 1024) @ (1024 x 1024)
    sgemm_k<<<dim3(DD / GBN, NTOK / GBM), 256>>>(abuf, w_out, out,
                                                 NTOK, DD, INNER);
}

// round 5
// speedup vs baseline: 2.0017x; 2.0017x over previous
#include <cuda_runtime.h>
#include <cuda_bf16.h>
#include <math.h>
#include <stdint.h>

#define BB     2
#define SS     4096
#define DD     1024
#define HH     16
#define DH     64
#define SEGLEN 512
#define PP     16
#define NWIN   8
#define INNER  1024
#define NTOK   (BB * SS)   // 8192

// ---------------- scratch (device globals; no allocation allowed) ----------
__device__ float          g_qkv[NTOK * 3 * INNER];     // 96 MB fp32 qkv
__device__ __nv_bfloat16  g_ah[NTOK * DD];             // rmsnorm out hi
__device__ __nv_bfloat16  g_al[NTOK * DD];             // rmsnorm out lo
__device__ __nv_bfloat16  g_ch[NTOK * INNER];          // attn out hi
__device__ __nv_bfloat16  g_cl[NTOK * INNER];          // attn out lo
__device__ __nv_bfloat16  g_bhq[3 * INNER * DD];       // w_qkv^T hi  [N,K]
__device__ __nv_bfloat16  g_blq[3 * INNER * DD];       // w_qkv^T lo
__device__ __nv_bfloat16  g_bho[DD * INNER];           // w_out^T hi
__device__ __nv_bfloat16  g_blo[DD * INNER];           // w_out^T lo

// ---------------- PTX helpers (sm_80-class only; no 'a'-features) ----------
__device__ __forceinline__ uint32_t smem_u32(const void* p) {
    uint32_t a;
    asm("{ .reg .u64 t; cvta.to.shared.u64 t, %1; cvt.u32.u64 %0, t; }" : "=r"(a) : "l"(p));
    return a;
}

#define CP_ASYNC16(saddr, gptr) \
    asm volatile("cp.async.cg.shared.global [%0], [%1], 16;" :: "r"(saddr), "l"(gptr))
#define CP_COMMIT() asm volatile("cp.async.commit_group;" ::: "memory")
#define CP_WAIT(n)  asm volatile("cp.async.wait_group %0;" :: "n"(n) : "memory")

#define LDSM4(r, a)                                                                 \
    asm volatile("ldmatrix.sync.aligned.m8n8.x4.shared.b16 {%0,%1,%2,%3}, [%4];"    \
        : "=r"((r)[0]), "=r"((r)[1]), "=r"((r)[2]), "=r"((r)[3]) : "r"(a))

#define MMA_BF16(d, a, b)                                                           \
    asm volatile("mma.sync.aligned.m16n8k16.row.col.f32.bf16.bf16.f32 "             \
        "{%0,%1,%2,%3}, {%4,%5,%6,%7}, {%8,%9}, {%0,%1,%2,%3};"                     \
        : "+f"((d)[0]), "+f"((d)[1]), "+f"((d)[2]), "+f"((d)[3])                    \
        : "r"((a)[0]), "r"((a)[1]), "r"((a)[2]), "r"((a)[3]), "r"((b)[0]), "r"((b)[1]))

// ---------------------------------------------------------------------------
// Kernel 1: RMSNorm fused with bf16 hi/lo split.
// ---------------------------------------------------------------------------
__global__ __launch_bounds__(256) void rmsnorm_split_k(const float* __restrict__ x,
                                                       const float* __restrict__ gamma,
                                                       __nv_bfloat16* __restrict__ Ah,
                                                       __nv_bfloat16* __restrict__ Al) {
    int row = blockIdx.x;
    int t = threadIdx.x;
    const float4* xr = reinterpret_cast<const float4*>(x + (size_t)row * DD);
    const float4* gr = reinterpret_cast<const float4*>(gamma);

    float4 v = xr[t];
    float ss = v.x * v.x + v.y * v.y + v.z * v.z + v.w * v.w;
    #pragma unroll
    for (int o = 16; o > 0; o >>= 1) ss += __shfl_xor_sync(0xffffffffu, ss, o);

    __shared__ float red[8];
    int warp = t >> 5, lane = t & 31;
    if (lane == 0) red[warp] = ss;
    __syncthreads();
    if (warp == 0) {
        float s2 = (lane < 8) ? red[lane] : 0.0f;
        #pragma unroll
        for (int o = 16; o > 0; o >>= 1) s2 += __shfl_xor_sync(0xffffffffu, s2, o);
        if (lane == 0) red[0] = s2;
    }
    __syncthreads();

    float inv = rsqrtf(red[0] * (1.0f / DD) + 1e-6f);
    float4 g = gr[t];
    float o[4] = { v.x * inv * g.x, v.y * inv * g.y, v.z * inv * g.z, v.w * inv * g.w };

    union { __nv_bfloat16 b[4]; uint2 u; } hi, lo;
    #pragma unroll
    for (int j = 0; j < 4; j++) {
        hi.b[j] = __float2bfloat16(o[j]);
        lo.b[j] = __float2bfloat16(o[j] - __bfloat162float(hi.b[j]));
    }
    size_t off = (size_t)row * DD + t * 4;
    *reinterpret_cast<uint2*>(Ah + off) = hi.u;
    *reinterpret_cast<uint2*>(Al + off) = lo.u;
}

// ---------------------------------------------------------------------------
// Kernel 2: weight transpose + split.  W[K,N] fp32 -> Bh/Bl[N,K] bf16.
// ---------------------------------------------------------------------------
__global__ __launch_bounds__(256) void tsplit_k(const float* __restrict__ W,
                                                __nv_bfloat16* __restrict__ Bh,
                                                __nv_bfloat16* __restrict__ Bl,
                                                int K, int N) {
    __shared__ float tile[32][33];
    int n0 = blockIdx.x * 32, k0 = blockIdx.y * 32;
    int tx = threadIdx.x & 31, ty = threadIdx.x >> 5;   // ty 0..7
    #pragma unroll
    for (int i = 0; i < 32; i += 8)
        tile[ty + i][tx] = W[(size_t)(k0 + ty + i) * N + n0 + tx];
    __syncthreads();
    #pragma unroll
    for (int i = 0; i < 32; i += 8) {
        float v = tile[tx][ty + i];
        __nv_bfloat16 h = __float2bfloat16(v);
        __nv_bfloat16 l = __float2bfloat16(v - __bfloat162float(h));
        size_t o = (size_t)(n0 + ty + i) * K + k0 + tx;
        Bh[o] = h;
        Bl[o] = l;
    }
}

// ---------------------------------------------------------------------------
// Kernel 3: HMMA (mma.sync bf16) GEMM, 3-term split:
//   C fp32[M,N] = (Ah+Al)[M,K] @ ((Bh+Bl)[N,K])^T
// 128x128 CTA tile, 8 warps (2x4), 64x32 per warp, BK=64 double-buffered via
// cp.async, XOR-16B smem swizzle, ldmatrix fragments.
// ---------------------------------------------------------------------------
#define TILEB   16384                  // one 128x64 bf16 tile: 128 rows x 128B
#define BUFB    (4 * TILEB)            // Ah, Al, Bh, Bl
#define GSMEM   (2 * BUFB)             // 128 KB double-buffered

__global__ __launch_bounds__(256, 1) void gemm_mma_k(const __nv_bfloat16* __restrict__ Ah,
                                                     const __nv_bfloat16* __restrict__ Al,
                                                     const __nv_bfloat16* __restrict__ Bh,
                                                     const __nv_bfloat16* __restrict__ Bl,
                                                     float* __restrict__ C,
                                                     int M, int N, int K) {
    extern __shared__ __align__(1024) char smem[];
    uint32_t sb = smem_u32(smem);
    const int tid = threadIdx.x;
    const int lane = tid & 31;
    const int wid = tid >> 5;
    const int m0 = blockIdx.y * 128, n0 = blockIdx.x * 128;
    const int wm = (wid & 1) * 64;      // warp M offset within tile
    const int wn = (wid >> 1) * 32;     // warp N offset within tile

    float acc[4][4][4];
    #pragma unroll
    for (int i = 0; i < 4; i++)
        #pragma unroll
        for (int j = 0; j < 4; j++)
            #pragma unroll
            for (int r = 0; r < 4; r++) acc[i][j][r] = 0.0f;

    const int NC = K >> 6;

    // stage one BK=64 chunk (4 tiles) into smem buffer via cp.async
    auto issue = [&](int c) {
        int buf = c & 1;
        uint32_t base = sb + buf * BUFB;
        const __nv_bfloat16* gsrc[4] = {
            Ah + (size_t)m0 * K + c * 64,
            Al + (size_t)m0 * K + c * 64,
            Bh + (size_t)n0 * K + c * 64,
            Bl + (size_t)n0 * K + c * 64
        };
        #pragma unroll
        for (int tile = 0; tile < 4; ++tile) {
            #pragma unroll
            for (int it = 0; it < 4; ++it) {
                int lin = tid + it * 256;         // 1024 16B-chunks per tile
                int r = lin >> 3, s = lin & 7;
                uint32_t dst = base + tile * TILEB + r * 128 + ((s ^ (r & 7)) << 4);
                const char* src = (const char*)(gsrc[tile] + (size_t)r * K + s * 8);
                CP_ASYNC16(dst, src);
            }
        }
        CP_COMMIT();
    };

    issue(0);

    // per-lane ldmatrix base indices
    const int ra  = wm + (lane & 15);        // A row for this lane
    const int sa  = ra & 7;                  // A swizzle key
    const int ha  = lane >> 4;               // A k-half (0/1)
    const int rbl = (lane & 7) + ((lane >> 4) << 3);  // B row offset within 16-row pair
    const int hb  = (lane >> 3) & 1;         // B k-half
    const int sbz = rbl & 7;

    for (int c = 0; c < NC; ++c) {
        if (c + 1 < NC) { issue(c + 1); CP_WAIT(1); }
        else           { CP_WAIT(0); }
        __syncthreads();

        uint32_t base = sb + (c & 1) * BUFB;
        #pragma unroll
        for (int ks = 0; ks < 4; ++ks) {
            const int kc = ks * 2;

            uint32_t aH[4][4];
            #pragma unroll
            for (int mt = 0; mt < 4; ++mt) {
                uint32_t ad = base + (ra + mt * 16) * 128 + (((kc + ha) ^ sa) << 4);
                LDSM4(aH[mt], ad);
            }
            uint32_t bH[4][2];
            #pragma unroll
            for (int np = 0; np < 2; ++np) {
                uint32_t t4[4];
                uint32_t ad = base + 2 * TILEB + (wn + np * 16 + rbl) * 128
                            + (((kc + hb) ^ sbz) << 4);
                LDSM4(t4, ad);
                bH[np * 2][0] = t4[0]; bH[np * 2][1] = t4[1];
                bH[np * 2 + 1][0] = t4[2]; bH[np * 2 + 1][1] = t4[3];
            }
            #pragma unroll
            for (int mt = 0; mt < 4; ++mt)
                #pragma unroll
                for (int nt = 0; nt < 4; ++nt)
                    MMA_BF16(acc[mt][nt], aH[mt], bH[nt]);

            uint32_t bL[4][2];
            #pragma unroll
            for (int np = 0; np < 2; ++np) {
                uint32_t t4[4];
                uint32_t ad = base + 3 * TILEB + (wn + np * 16 + rbl) * 128
                            + (((kc + hb) ^ sbz) << 4);
                LDSM4(t4, ad);
                bL[np * 2][0] = t4[0]; bL[np * 2][1] = t4[1];
                bL[np * 2 + 1][0] = t4[2]; bL[np * 2 + 1][1] = t4[3];
            }
            #pragma unroll
            for (int mt = 0; mt < 4; ++mt)
                #pragma unroll
                for (int nt = 0; nt < 4; ++nt)
                    MMA_BF16(acc[mt][nt], aH[mt], bL[nt]);

            uint32_t aL[4][4];
            #pragma unroll
            for (int mt = 0; mt < 4; ++mt) {
                uint32_t ad = base + TILEB + (ra + mt * 16) * 128 + (((kc + ha) ^ sa) << 4);
                LDSM4(aL[mt], ad);
            }
            #pragma unroll
            for (int mt = 0; mt < 4; ++mt)
                #pragma unroll
                for (int nt = 0; nt < 4; ++nt)
                    MMA_BF16(acc[mt][nt], aL[mt], bH[nt]);
        }
        __syncthreads();
    }

    // epilogue
    #pragma unroll
    for (int mt = 0; mt < 4; ++mt) {
        #pragma unroll
        for (int nt = 0; nt < 4; ++nt) {
            int row = m0 + wm + mt * 16 + (lane >> 2);
            int col = n0 + wn + nt * 8 + (lane & 3) * 2;
            *reinterpret_cast<float2*>(C + (size_t)row * N + col) =
                make_float2(acc[mt][nt][0], acc[mt][nt][1]);
            *reinterpret_cast<float2*>(C + (size_t)(row + 8) * N + col) =
                make_float2(acc[mt][nt][2], acc[mt][nt][3]);
        }
    }
}

// ---------------------------------------------------------------------------
// Kernel 4: windowed attention with memory tokens; writes bf16 hi/lo.
// ---------------------------------------------------------------------------
__global__ __launch_bounds__(128) void attn_k(const float* __restrict__ qkv,
                                              const float* __restrict__ pmk,
                                              const float* __restrict__ pmv,
                                              __nv_bfloat16* __restrict__ outh,
                                              __nv_bfloat16* __restrict__ outl) {
    int qt = blockIdx.x;
    int wh = blockIdx.y;
    int b  = blockIdx.z;
    int w = wh >> 4;
    int hd = wh & 15;
    int t = threadIdx.x;
    int i = qt * 128 + t;
    size_t tok = (size_t)(b * SS + w * SEGLEN + i);

    __shared__ float4 Ks[32][16];
    __shared__ float4 Vs[32][16];

    const float sc = 0.125f;
    float4 q4[16];
    const float4* qp = reinterpret_cast<const float4*>(qkv + tok * 3072 + hd * 64);
    #pragma unroll
    for (int r = 0; r < 16; r++) {
        float4 v = qp[r];
        q4[r] = make_float4(v.x * sc, v.y * sc, v.z * sc, v.w * sc);
    }

    float m = -INFINITY, l = 0.0f;
    float4 acc[16];
    #pragma unroll
    for (int r = 0; r < 16; r++) acc[r] = make_float4(0.f, 0.f, 0.f, 0.f);

    const int total = SEGLEN + PP;
    int kmax = min(total - 1, qt * 128 + 127 + PP);
    int nch = (kmax >> 5) + 1;

    for (int c = 0; c < nch; c++) {
        int c0 = c * 32;
        int nk = min(32, total - c0);

        #pragma unroll
        for (int r = 0; r < 4; r++) {
            int idx = t + 128 * r;
            int j = idx >> 4;
            int f = idx & 15;
            if (j < nk) {
                int gj = c0 + j;
                const float4 *kp, *vp;
                if (gj < PP) {
                    kp = reinterpret_cast<const float4*>(pmk + (hd * PP + gj) * 64);
                    vp = reinterpret_cast<const float4*>(pmv + (hd * PP + gj) * 64);
                } else {
                    size_t ktok = (size_t)(b * SS + w * SEGLEN + (gj - PP));
                    kp = reinterpret_cast<const float4*>(qkv + ktok * 3072 + 1024 + hd * 64);
                    vp = reinterpret_cast<const float4*>(qkv + ktok * 3072 + 2048 + hd * 64);
                }
                Ks[j][f] = kp[f];
                Vs[j][f] = vp[f];
            }
        }
        __syncthreads();

        int jv = min(nk - 1, i + PP - c0);
        float s[32];
        float smax = -INFINITY;
        #pragma unroll
        for (int j = 0; j < 32; j++) {
            if (j <= jv) {
                float d = 0.0f;
                #pragma unroll
                for (int r = 0; r < 16; r++) {
                    float4 kk = Ks[j][r];
                    d += q4[r].x * kk.x + q4[r].y * kk.y + q4[r].z * kk.z + q4[r].w * kk.w;
                }
                s[j] = d;
                smax = fmaxf(smax, d);
            } else {
                s[j] = -INFINITY;
            }
        }

        if (jv >= 0) {
            float newm = fmaxf(m, smax);
            float corr = __expf(m - newm);
            l *= corr;
            #pragma unroll
            for (int r = 0; r < 16; r++) {
                acc[r].x *= corr; acc[r].y *= corr;
                acc[r].z *= corr; acc[r].w *= corr;
            }
            m = newm;
            #pragma unroll
            for (int j = 0; j < 32; j++) {
                if (j <= jv) {
                    float p = __expf(s[j] - m);
                    l += p;
                    #pragma unroll
                    for (int r = 0; r < 16; r++) {
                        float4 vv = Vs[j][r];
                        acc[r].x += p * vv.x; acc[r].y += p * vv.y;
                        acc[r].z += p * vv.z; acc[r].w += p * vv.w;
                    }
                }
            }
        }
        __syncthreads();
    }

    float invl = 1.0f / l;
    __nv_bfloat16* hp = outh + tok * 1024 + hd * 64;
    __nv_bfloat16* lp = outl + tok * 1024 + hd * 64;
    #pragma unroll
    for (int r = 0; r < 16; r++) {
        float o[4] = { acc[r].x * invl, acc[r].y * invl, acc[r].z * invl, acc[r].w * invl };
        union { __nv_bfloat16 b[4]; uint2 u; } hi, lo;
        #pragma unroll
        for (int j = 0; j < 4; j++) {
            hi.b[j] = __float2bfloat16(o[j]);
            lo.b[j] = __float2bfloat16(o[j] - __bfloat162float(hi.b[j]));
        }
        *reinterpret_cast<uint2*>(hp + r * 4) = hi.u;
        *reinterpret_cast<uint2*>(lp + r * 4) = lo.u;
    }
}

// ---------------------------------------------------------------------------
extern "C" void kernel_launch(void* const* d_in, const int* in_sizes, int n_in,
                              void* d_out, int out_size) {
    const float* x     = (const float*)d_in[0];
    const float* gamma = (const float*)d_in[1];
    const float* w_qkv = (const float*)d_in[2];
    const float* w_out = (const float*)d_in[3];
    const float* pm_k  = (const float*)d_in[4];
    const float* pm_v  = (const float*)d_in[5];
    float* out = (float*)d_out;

    float* qkv;
    __nv_bfloat16 *ah, *al, *ch, *cl, *bhq, *blq, *bho, *blo;
    cudaGetSymbolAddress((void**)&qkv, g_qkv);
    cudaGetSymbolAddress((void**)&ah,  g_ah);
    cudaGetSymbolAddress((void**)&al,  g_al);
    cudaGetSymbolAddress((void**)&ch,  g_ch);
    cudaGetSymbolAddress((void**)&cl,  g_cl);
    cudaGetSymbolAddress((void**)&bhq, g_bhq);
    cudaGetSymbolAddress((void**)&blq, g_blq);
    cudaGetSymbolAddress((void**)&bho, g_bho);
    cudaGetSymbolAddress((void**)&blo, g_blo);

    cudaFuncSetAttribute(gemm_mma_k, cudaFuncAttributeMaxDynamicSharedMemorySize, GSMEM);

    // 1) RMSNorm + split
    rmsnorm_split_k<<<NTOK, 256>>>(x, gamma, ah, al);

    // 2) weight prep: transpose + split
    tsplit_k<<<dim3(3 * INNER / 32, DD / 32), 256>>>(w_qkv, bhq, blq, DD, 3 * INNER);
    tsplit_k<<<dim3(DD / 32, INNER / 32), 256>>>(w_out, bho, blo, INNER, DD);

    // 3) QKV projection: (8192x1024) @ (1024x3072) on tensor cores
    gemm_mma_k<<<dim3(3 * INNER / 128, NTOK / 128), 256, GSMEM>>>(
        ah, al, bhq, blq, qkv, NTOK, 3 * INNER, DD);

    // 4) Attention (writes bf16 hi/lo)
    attn_k<<<dim3(SEGLEN / 128, NWIN * HH, BB), 128>>>(qkv, pm_k, pm_v, ch, cl);

    // 5) Output projection: (8192x1024) @ (1024x1024) on tensor cores
    gemm_mma_k<<<dim3(DD / 128, NTOK / 128), 256, GSMEM>>>(
        ch, cl, bho, blo, out, NTOK, DD, INNER);
}

// round 6
// speedup vs baseline: 3.4073x; 1.7022x over previous
#include <cuda_runtime.h>
#include <cuda_bf16.h>
#include <math.h>
#include <stdint.h>

#define BB     2
#define SS     4096
#define DD     1024
#define HH     16
#define DH     64
#define SEGLEN 512
#define PP     16
#define NWIN   8
#define INNER  1024
#define NTOK   (BB * SS)   // 8192
#define TOTKEY (SEGLEN + PP)  // 528

// ---------------- scratch (device globals; no allocation allowed) ----------
__device__ __nv_bfloat16  g_qh[NTOK * 3 * INNER];      // qkv split hi (48MB)
__device__ __nv_bfloat16  g_ql[NTOK * 3 * INNER];      // qkv split lo
__device__ __nv_bfloat16  g_ah[NTOK * DD];             // rmsnorm out hi
__device__ __nv_bfloat16  g_al[NTOK * DD];             // rmsnorm out lo
__device__ __nv_bfloat16  g_ch[NTOK * INNER];          // attn out hi
__device__ __nv_bfloat16  g_cl[NTOK * INNER];          // attn out lo
__device__ __nv_bfloat16  g_bhq[3 * INNER * DD];       // w_qkv^T hi  [N,K]
__device__ __nv_bfloat16  g_blq[3 * INNER * DD];       // w_qkv^T lo
__device__ __nv_bfloat16  g_bho[DD * INNER];           // w_out^T hi
__device__ __nv_bfloat16  g_blo[DD * INNER];           // w_out^T lo
__device__ __nv_bfloat16  g_pmkh[HH * PP * DH];        // pm_k hi
__device__ __nv_bfloat16  g_pmkl[HH * PP * DH];
__device__ __nv_bfloat16  g_pmvh[HH * PP * DH];        // pm_v hi
__device__ __nv_bfloat16  g_pmvl[HH * PP * DH];

// ---------------- PTX helpers (sm_80-class only; no 'a'-features) ----------
__device__ __forceinline__ uint32_t smem_u32(const void* p) {
    uint32_t a;
    asm("{ .reg .u64 t; cvta.to.shared.u64 t, %1; cvt.u32.u64 %0, t; }" : "=r"(a) : "l"(p));
    return a;
}

#define CP_ASYNC16(saddr, gptr) \
    asm volatile("cp.async.cg.shared.global [%0], [%1], 16;" :: "r"(saddr), "l"(gptr))
#define CP_COMMIT() asm volatile("cp.async.commit_group;" ::: "memory")
#define CP_WAIT(n)  asm volatile("cp.async.wait_group %0;" :: "n"(n) : "memory")

#define LDSM4(r, a)                                                                 \
    asm volatile("ldmatrix.sync.aligned.m8n8.x4.shared.b16 {%0,%1,%2,%3}, [%4];"    \
        : "=r"((r)[0]), "=r"((r)[1]), "=r"((r)[2]), "=r"((r)[3]) : "r"(a))

#define LDSM4T(r, a)                                                                \
    asm volatile("ldmatrix.sync.aligned.m8n8.x4.trans.shared.b16 {%0,%1,%2,%3}, [%4];" \
        : "=r"((r)[0]), "=r"((r)[1]), "=r"((r)[2]), "=r"((r)[3]) : "r"(a))

#define MMA_BF16(d, a, b)                                                           \
    asm volatile("mma.sync.aligned.m16n8k16.row.col.f32.bf16.bf16.f32 "             \
        "{%0,%1,%2,%3}, {%4,%5,%6,%7}, {%8,%9}, {%0,%1,%2,%3};"                     \
        : "+f"((d)[0]), "+f"((d)[1]), "+f"((d)[2]), "+f"((d)[3])                    \
        : "r"((a)[0]), "r"((a)[1]), "r"((a)[2]), "r"((a)[3]), "r"((b)[0]), "r"((b)[1]))

__device__ __forceinline__ uint32_t packbf(float x, float y) {
    __nv_bfloat162 t = __floats2bfloat162_rn(x, y);
    return *reinterpret_cast<uint32_t*>(&t);
}
// hi/lo split of a pair of floats into two packed bf16x2 regs
__device__ __forceinline__ void split2(float x, float y, uint32_t& ph, uint32_t& pl) {
    __nv_bfloat16 hx = __float2bfloat16(x), hy = __float2bfloat16(y);
    ph = packbf(__bfloat162float(hx), __bfloat162float(hy));  // exact
    pl = packbf(x - __bfloat162float(hx), y - __bfloat162float(hy));
}

// ---------------------------------------------------------------------------
// Kernel 1: RMSNorm fused with bf16 hi/lo split.
// ---------------------------------------------------------------------------
__global__ __launch_bounds__(256) void rmsnorm_split_k(const float* __restrict__ x,
                                                       const float* __restrict__ gamma,
                                                       __nv_bfloat16* __restrict__ Ah,
                                                       __nv_bfloat16* __restrict__ Al) {
    int row = blockIdx.x;
    int t = threadIdx.x;
    const float4* xr = reinterpret_cast<const float4*>(x + (size_t)row * DD);
    const float4* gr = reinterpret_cast<const float4*>(gamma);

    float4 v = xr[t];
    float ss = v.x * v.x + v.y * v.y + v.z * v.z + v.w * v.w;
    #pragma unroll
    for (int o = 16; o > 0; o >>= 1) ss += __shfl_xor_sync(0xffffffffu, ss, o);

    __shared__ float red[8];
    int warp = t >> 5, lane = t & 31;
    if (lane == 0) red[warp] = ss;
    __syncthreads();
    if (warp == 0) {
        float s2 = (lane < 8) ? red[lane] : 0.0f;
        #pragma unroll
        for (int o = 16; o > 0; o >>= 1) s2 += __shfl_xor_sync(0xffffffffu, s2, o);
        if (lane == 0) red[0] = s2;
    }
    __syncthreads();

    float inv = rsqrtf(red[0] * (1.0f / DD) + 1e-6f);
    float4 g = gr[t];
    float o[4] = { v.x * inv * g.x, v.y * inv * g.y, v.z * inv * g.z, v.w * inv * g.w };

    union { __nv_bfloat16 b[4]; uint2 u; } hi, lo;
    #pragma unroll
    for (int j = 0; j < 4; j++) {
        hi.b[j] = __float2bfloat16(o[j]);
        lo.b[j] = __float2bfloat16(o[j] - __bfloat162float(hi.b[j]));
    }
    size_t off = (size_t)row * DD + t * 4;
    *reinterpret_cast<uint2*>(Ah + off) = hi.u;
    *reinterpret_cast<uint2*>(Al + off) = lo.u;
}

// ---------------------------------------------------------------------------
// Kernel 2: weight transpose + split.  W[K,N] fp32 -> Bh/Bl[N,K] bf16.
// ---------------------------------------------------------------------------
__global__ __launch_bounds__(256) void tsplit_k(const float* __restrict__ W,
                                                __nv_bfloat16* __restrict__ Bh,
                                                __nv_bfloat16* __restrict__ Bl,
                                                int K, int N) {
    __shared__ float tile[32][33];
    int n0 = blockIdx.x * 32, k0 = blockIdx.y * 32;
    int tx = threadIdx.x & 31, ty = threadIdx.x >> 5;
    #pragma unroll
    for (int i = 0; i < 32; i += 8)
        tile[ty + i][tx] = W[(size_t)(k0 + ty + i) * N + n0 + tx];
    __syncthreads();
    #pragma unroll
    for (int i = 0; i < 32; i += 8) {
        float v = tile[tx][ty + i];
        __nv_bfloat16 h = __float2bfloat16(v);
        __nv_bfloat16 l = __float2bfloat16(v - __bfloat162float(h));
        size_t o = (size_t)(n0 + ty + i) * K + k0 + tx;
        Bh[o] = h;
        Bl[o] = l;
    }
}

// ---------------------------------------------------------------------------
// Kernel 2b: persistent-memory token split (tiny).
// ---------------------------------------------------------------------------
__global__ __launch_bounds__(256) void pmsplit_k(const float* __restrict__ pk,
                                                 const float* __restrict__ pv,
                                                 __nv_bfloat16* kh, __nv_bfloat16* kl,
                                                 __nv_bfloat16* vh, __nv_bfloat16* vl) {
    int i = blockIdx.x * 256 + threadIdx.x;
    if (i < HH * PP * DH) {
        float a = pk[i];
        __nv_bfloat16 h = __float2bfloat16(a);
        kh[i] = h; kl[i] = __float2bfloat16(a - __bfloat162float(h));
        float b = pv[i];
        h = __float2bfloat16(b);
        vh[i] = h; vl[i] = __float2bfloat16(b - __bfloat162float(h));
    }
}

// ---------------------------------------------------------------------------
// Kernel 3: HMMA GEMM, 3-term split. Templated epilogue: fp32 or bf16-split.
// ---------------------------------------------------------------------------
#define TILEB   16384
#define BUFB    (4 * TILEB)
#define GSMEM   (2 * BUFB)

template <bool SPLIT>
__global__ __launch_bounds__(256, 1) void gemm_mma_k(const __nv_bfloat16* __restrict__ Ah,
                                                     const __nv_bfloat16* __restrict__ Al,
                                                     const __nv_bfloat16* __restrict__ Bh,
                                                     const __nv_bfloat16* __restrict__ Bl,
                                                     float* __restrict__ C,
                                                     __nv_bfloat16* __restrict__ Ch,
                                                     __nv_bfloat16* __restrict__ Cl,
                                                     int M, int N, int K) {
    extern __shared__ __align__(1024) char smem[];
    uint32_t sb = smem_u32(smem);
    const int tid = threadIdx.x;
    const int lane = tid & 31;
    const int wid = tid >> 5;
    const int m0 = blockIdx.y * 128, n0 = blockIdx.x * 128;
    const int wm = (wid & 1) * 64;
    const int wn = (wid >> 1) * 32;

    float acc[4][4][4];
    #pragma unroll
    for (int i = 0; i < 4; i++)
        #pragma unroll
        for (int j = 0; j < 4; j++)
            #pragma unroll
            for (int r = 0; r < 4; r++) acc[i][j][r] = 0.0f;

    const int NC = K >> 6;

    auto issue = [&](int c) {
        int buf = c & 1;
        uint32_t base = sb + buf * BUFB;
        const __nv_bfloat16* gsrc[4] = {
            Ah + (size_t)m0 * K + c * 64,
            Al + (size_t)m0 * K + c * 64,
            Bh + (size_t)n0 * K + c * 64,
            Bl + (size_t)n0 * K + c * 64
        };
        #pragma unroll
        for (int tile = 0; tile < 4; ++tile) {
            #pragma unroll
            for (int it = 0; it < 4; ++it) {
                int lin = tid + it * 256;
                int r = lin >> 3, s = lin & 7;
                uint32_t dst = base + tile * TILEB + r * 128 + ((s ^ (r & 7)) << 4);
                const char* src = (const char*)(gsrc[tile] + (size_t)r * K + s * 8);
                CP_ASYNC16(dst, src);
            }
        }
        CP_COMMIT();
    };

    issue(0);

    const int ra  = wm + (lane & 15);
    const int sa  = ra & 7;
    const int ha  = lane >> 4;
    const int rbl = (lane & 7) + ((lane >> 4) << 3);
    const int hb  = (lane >> 3) & 1;
    const int sbz = rbl & 7;

    for (int c = 0; c < NC; ++c) {
        if (c + 1 < NC) { issue(c + 1); CP_WAIT(1); }
        else           { CP_WAIT(0); }
        __syncthreads();

        uint32_t base = sb + (c & 1) * BUFB;
        #pragma unroll
        for (int ks = 0; ks < 4; ++ks) {
            const int kc = ks * 2;

            uint32_t aH[4][4];
            #pragma unroll
            for (int mt = 0; mt < 4; ++mt) {
                uint32_t ad = base + (ra + mt * 16) * 128 + (((kc + ha) ^ sa) << 4);
                LDSM4(aH[mt], ad);
            }
            uint32_t bH[4][2];
            #pragma unroll
            for (int np = 0; np < 2; ++np) {
                uint32_t t4[4];
                uint32_t ad = base + 2 * TILEB + (wn + np * 16 + rbl) * 128
                            + (((kc + hb) ^ sbz) << 4);
                LDSM4(t4, ad);
                bH[np * 2][0] = t4[0]; bH[np * 2][1] = t4[1];
                bH[np * 2 + 1][0] = t4[2]; bH[np * 2 + 1][1] = t4[3];
            }
            #pragma unroll
            for (int mt = 0; mt < 4; ++mt)
                #pragma unroll
                for (int nt = 0; nt < 4; ++nt)
                    MMA_BF16(acc[mt][nt], aH[mt], bH[nt]);

            uint32_t bL[4][2];
            #pragma unroll
            for (int np = 0; np < 2; ++np) {
                uint32_t t4[4];
                uint32_t ad = base + 3 * TILEB + (wn + np * 16 + rbl) * 128
                            + (((kc + hb) ^ sbz) << 4);
                LDSM4(t4, ad);
                bL[np * 2][0] = t4[0]; bL[np * 2][1] = t4[1];
                bL[np * 2 + 1][0] = t4[2]; bL[np * 2 + 1][1] = t4[3];
            }
            #pragma unroll
            for (int mt = 0; mt < 4; ++mt)
                #pragma unroll
                for (int nt = 0; nt < 4; ++nt)
                    MMA_BF16(acc[mt][nt], aH[mt], bL[nt]);

            uint32_t aL[4][4];
            #pragma unroll
            for (int mt = 0; mt < 4; ++mt) {
                uint32_t ad = base + TILEB + (ra + mt * 16) * 128 + (((kc + ha) ^ sa) << 4);
                LDSM4(aL[mt], ad);
            }
            #pragma unroll
            for (int mt = 0; mt < 4; ++mt)
                #pragma unroll
                for (int nt = 0; nt < 4; ++nt)
                    MMA_BF16(acc[mt][nt], aL[mt], bH[nt]);
        }
        __syncthreads();
    }

    #pragma unroll
    for (int mt = 0; mt < 4; ++mt) {
        #pragma unroll
        for (int nt = 0; nt < 4; ++nt) {
            int row = m0 + wm + mt * 16 + (lane >> 2);
            int col = n0 + wn + nt * 8 + (lane & 3) * 2;
            if (SPLIT) {
                uint32_t h0, l0, h1, l1;
                split2(acc[mt][nt][0], acc[mt][nt][1], h0, l0);
                split2(acc[mt][nt][2], acc[mt][nt][3], h1, l1);
                *reinterpret_cast<uint32_t*>(Ch + (size_t)row * N + col) = h0;
                *reinterpret_cast<uint32_t*>(Cl + (size_t)row * N + col) = l0;
                *reinterpret_cast<uint32_t*>(Ch + (size_t)(row + 8) * N + col) = h1;
                *reinterpret_cast<uint32_t*>(Cl + (size_t)(row + 8) * N + col) = l1;
            } else {
                *reinterpret_cast<float2*>(C + (size_t)row * N + col) =
                    make_float2(acc[mt][nt][0], acc[mt][nt][1]);
                *reinterpret_cast<float2*>(C + (size_t)(row + 8) * N + col) =
                    make_float2(acc[mt][nt][2], acc[mt][nt][3]);
            }
        }
    }
}

// ---------------------------------------------------------------------------
// Kernel 4: flash attention on mma.sync, 3-term bf16 split for S and PV.
// Block: 256 thr (8 warps), one (q-tile 128, window*head, batch).
// Warp w owns q-rows [w*16, w*16+16). K/V chunks of 64 keys, double-buffered.
// smem: Qh|Ql (32KB) + 2 x (Kh|Kl|Vh|Vl) (64KB) = 96KB.
// ---------------------------------------------------------------------------
#define AT_QH   0
#define AT_QL   16384
#define AT_KV   32768
#define AT_KVB  32768          // per-buffer size
#define AT_SMEM (AT_KV + 2 * AT_KVB)

__global__ __launch_bounds__(256, 1) void attn_mma_k(const __nv_bfloat16* __restrict__ qh,
                                                     const __nv_bfloat16* __restrict__ ql,
                                                     const __nv_bfloat16* __restrict__ pmkh,
                                                     const __nv_bfloat16* __restrict__ pmkl,
                                                     const __nv_bfloat16* __restrict__ pmvh,
                                                     const __nv_bfloat16* __restrict__ pmvl,
                                                     __nv_bfloat16* __restrict__ outh,
                                                     __nv_bfloat16* __restrict__ outl) {
    extern __shared__ __align__(1024) char smem[];
    uint32_t sb = smem_u32(smem);
    const int qt = blockIdx.x;
    const int wh = blockIdx.y;
    const int b  = blockIdx.z;
    const int w  = wh >> 4;
    const int hd = wh & 15;
    const int tid = threadIdx.x;
    const int lane = tid & 31;
    const int wid = tid >> 5;
    const int tokbase = b * SS + w * SEGLEN;

    // ---- stage Q (hi & lo) into swizzled smem ----
    {
        #pragma unroll
        for (int t2 = 0; t2 < 2; ++t2) {
            const __nv_bfloat16* src = t2 ? ql : qh;
            uint32_t dbase = sb + (t2 ? AT_QL : AT_QH);
            #pragma unroll
            for (int it = 0; it < 4; ++it) {
                int lin = tid + it * 256;
                int r = lin >> 3, s = lin & 7;
                CP_ASYNC16(dbase + r * 128 + ((s ^ (r & 7)) << 4),
                           src + (size_t)(tokbase + qt * 128 + r) * 3072 + hd * 64 + s * 8);
            }
        }
        CP_COMMIT();
    }

    const int nch = ((qt * 128 + 127 + PP) >> 6) + 1;

    // ---- K/V chunk staging ----
    auto stage = [&](int c, int buf) {
        int c0 = c * 64;
        uint32_t base = sb + AT_KV + buf * AT_KVB;
        #pragma unroll
        for (int tile = 0; tile < 4; ++tile) {
            const __nv_bfloat16* pmsrc = (tile == 0) ? pmkh : (tile == 1) ? pmkl
                                       : (tile == 2) ? pmvh : pmvl;
            const __nv_bfloat16* tsrc  = (tile & 1) ? ql : qh;
            const int toff = (tile < 2) ? 1024 : 2048;
            #pragma unroll
            for (int it = 0; it < 2; ++it) {
                int lin = tid + it * 256;
                int r = lin >> 3, s = lin & 7;
                int j = c0 + r;
                uint32_t dst = base + tile * 8192 + r * 128 + ((s ^ (r & 7)) << 4);
                if (j < PP) {
                    CP_ASYNC16(dst, pmsrc + (hd * PP + j) * 64 + s * 8);
                } else if (j < TOTKEY) {
                    CP_ASYNC16(dst, tsrc + (size_t)(tokbase + j - PP) * 3072 + toff + hd * 64 + s * 8);
                } else {
                    uint4 z = make_uint4(0, 0, 0, 0);
                    *reinterpret_cast<uint4*>(smem + (dst - sb)) = z;
                }
            }
        }
        CP_COMMIT();
    };

    stage(0, 0);
    CP_WAIT(0);
    __syncthreads();

    // ---- Q fragments (kept in registers) ----
    uint32_t qfh[4][4], qfl[4][4];
    const int ra = wid * 16 + (lane & 15);
    const int ha = lane >> 4;
    #pragma unroll
    for (int ks = 0; ks < 4; ++ks) {
        uint32_t ad = sb + AT_QH + ra * 128 + (((ks * 2 + ha) ^ (ra & 7)) << 4);
        LDSM4(qfh[ks], ad);
        LDSM4(qfl[ks], ad + AT_QL);
    }

    // per-thread softmax state (rows lr and lr+8)
    const int lr = lane >> 2;
    const int i0 = qt * 128 + wid * 16 + lr;
    const int i1 = i0 + 8;
    float m0 = -1e30f, m1 = -1e30f, l0 = 0.0f, l1 = 0.0f;
    float oacc[8][4];
    #pragma unroll
    for (int d = 0; d < 8; ++d)
        #pragma unroll
        for (int r = 0; r < 4; ++r) oacc[d][r] = 0.0f;

    const int rbl = (lane & 7) + ((lane >> 4) << 3);
    const int hb  = (lane >> 3) & 1;
    const int sbz = rbl & 7;
    const int vrow = lane & 15;           // trans-ldmatrix key row within 16
    const int vhi  = lane >> 4;           // dim-chunk selector

    for (int c = 0; c < nch; ++c) {
        if (c + 1 < nch) { stage(c + 1, (c + 1) & 1); CP_WAIT(1); }
        else            { CP_WAIT(0); }
        __syncthreads();

        uint32_t kb = sb + AT_KV + (c & 1) * AT_KVB;          // Kh
        uint32_t vb = kb + 2 * 8192;                          // Vh
        int c0 = c * 64;

        // ---- S = Q K^T (3-term) ----
        float sacc[8][4];
        #pragma unroll
        for (int n = 0; n < 8; ++n)
            #pragma unroll
            for (int r = 0; r < 4; ++r) sacc[n][r] = 0.0f;

        #pragma unroll
        for (int ks = 0; ks < 4; ++ks) {
            #pragma unroll
            for (int np = 0; np < 4; ++np) {
                uint32_t kh4[4], kl4[4];
                uint32_t ad = kb + (np * 16 + rbl) * 128 + (((ks * 2 + hb) ^ sbz) << 4);
                LDSM4(kh4, ad);
                LDSM4(kl4, ad + 8192);
                MMA_BF16(sacc[2 * np],     qfh[ks], (&kh4[0]));
                MMA_BF16(sacc[2 * np],     qfh[ks], (&kl4[0]));
                MMA_BF16(sacc[2 * np],     qfl[ks], (&kh4[0]));
                MMA_BF16(sacc[2 * np + 1], qfh[ks], (&kh4[2]));
                MMA_BF16(sacc[2 * np + 1], qfh[ks], (&kl4[2]));
                MMA_BF16(sacc[2 * np + 1], qfl[ks], (&kh4[2]));
            }
        }

        // ---- scale + mask + online softmax ----
        const float sc = 0.125f;
        float rm0 = -1e30f, rm1 = -1e30f;
        #pragma unroll
        for (int n = 0; n < 8; ++n) {
            int jb = c0 + n * 8 + (lane & 3) * 2;
            #pragma unroll
            for (int r = 0; r < 4; ++r) {
                int j = jb + (r & 1);
                int i = (r < 2) ? i0 : i1;
                bool valid = (j < PP) | (i + PP >= j);
                float z = valid ? sacc[n][r] * sc : -1e30f;
                sacc[n][r] = z;
                if (r < 2) rm0 = fmaxf(rm0, z); else rm1 = fmaxf(rm1, z);
            }
        }
        rm0 = fmaxf(rm0, __shfl_xor_sync(0xffffffffu, rm0, 1));
        rm0 = fmaxf(rm0, __shfl_xor_sync(0xffffffffu, rm0, 2));
        rm1 = fmaxf(rm1, __shfl_xor_sync(0xffffffffu, rm1, 1));
        rm1 = fmaxf(rm1, __shfl_xor_sync(0xffffffffu, rm1, 2));

        float mn0 = fmaxf(m0, rm0), mn1 = fmaxf(m1, rm1);
        float corr0 = __expf(m0 - mn0), corr1 = __expf(m1 - mn1);
        m0 = mn0; m1 = mn1;

        float rs0 = 0.0f, rs1 = 0.0f;
        #pragma unroll
        for (int n = 0; n < 8; ++n) {
            float p0 = __expf(sacc[n][0] - m0);
            float p1 = __expf(sacc[n][1] - m0);
            float p2 = __expf(sacc[n][2] - m1);
            float p3 = __expf(sacc[n][3] - m1);
            sacc[n][0] = p0; sacc[n][1] = p1; sacc[n][2] = p2; sacc[n][3] = p3;
            rs0 += p0 + p1; rs1 += p2 + p3;
        }
        rs0 += __shfl_xor_sync(0xffffffffu, rs0, 1);
        rs0 += __shfl_xor_sync(0xffffffffu, rs0, 2);
        rs1 += __shfl_xor_sync(0xffffffffu, rs1, 1);
        rs1 += __shfl_xor_sync(0xffffffffu, rs1, 2);
        l0 = l0 * corr0 + rs0;
        l1 = l1 * corr1 + rs1;

        #pragma unroll
        for (int d = 0; d < 8; ++d) {
            oacc[d][0] *= corr0; oacc[d][1] *= corr0;
            oacc[d][2] *= corr1; oacc[d][3] *= corr1;
        }

        // ---- O += P V (3-term; P fragments built from sacc in-register) ----
        #pragma unroll
        for (int ks = 0; ks < 4; ++ks) {
            uint32_t pah[4], pal[4];
            split2(sacc[2 * ks][0],     sacc[2 * ks][1],     pah[0], pal[0]);
            split2(sacc[2 * ks][2],     sacc[2 * ks][3],     pah[1], pal[1]);
            split2(sacc[2 * ks + 1][0], sacc[2 * ks + 1][1], pah[2], pal[2]);
            split2(sacc[2 * ks + 1][2], sacc[2 * ks + 1][3], pah[3], pal[3]);

            #pragma unroll
            for (int dt2 = 0; dt2 < 4; ++dt2) {
                int krow = ks * 16 + vrow;
                uint32_t ad = vb + krow * 128 + (((dt2 * 2 + vhi) ^ (krow & 7)) << 4);
                uint32_t vh4[4], vl4[4];
                LDSM4T(vh4, ad);
                LDSM4T(vl4, ad + 8192);
                MMA_BF16(oacc[2 * dt2],     pah, (&vh4[0]));
                MMA_BF16(oacc[2 * dt2],     pah, (&vl4[0]));
                MMA_BF16(oacc[2 * dt2],     pal, (&vh4[0]));
                MMA_BF16(oacc[2 * dt2 + 1], pah, (&vh4[2]));
                MMA_BF16(oacc[2 * dt2 + 1], pah, (&vl4[2]));
                MMA_BF16(oacc[2 * dt2 + 1], pal, (&vh4[2]));
            }
        }
        __syncthreads();
    }

    // ---- finalize and write hi/lo bf16 ----
    float il0 = 1.0f / l0, il1 = 1.0f / l1;
    size_t tok0 = (size_t)tokbase + i0;
    size_t tok1 = (size_t)tokbase + i1;
    #pragma unroll
    for (int d = 0; d < 8; ++d) {
        int col = hd * 64 + d * 8 + (lane & 3) * 2;
        uint32_t h0, lo0, h1, lo1;
        split2(oacc[d][0] * il0, oacc[d][1] * il0, h0, lo0);
        split2(oacc[d][2] * il1, oacc[d][3] * il1, h1, lo1);
        *reinterpret_cast<uint32_t*>(outh + tok0 * 1024 + col) = h0;
        *reinterpret_cast<uint32_t*>(outl + tok0 * 1024 + col) = lo0;
        *reinterpret_cast<uint32_t*>(outh + tok1 * 1024 + col) = h1;
        *reinterpret_cast<uint32_t*>(outl + tok1 * 1024 + col) = lo1;
    }
}

// ---------------------------------------------------------------------------
extern "C" void kernel_launch(void* const* d_in, const int* in_sizes, int n_in,
                              void* d_out, int out_size) {
    const float* x     = (const float*)d_in[0];
    const float* gamma = (const float*)d_in[1];
    const float* w_qkv = (const float*)d_in[2];
    const float* w_out = (const float*)d_in[3];
    const float* pm_k  = (const float*)d_in[4];
    const float* pm_v  = (const float*)d_in[5];
    float* out = (float*)d_out;

    __nv_bfloat16 *qh, *ql, *ah, *al, *ch, *cl, *bhq, *blq, *bho, *blo;
    __nv_bfloat16 *pmkh, *pmkl, *pmvh, *pmvl;
    cudaGetSymbolAddress((void**)&qh,  g_qh);
    cudaGetSymbolAddress((void**)&ql,  g_ql);
    cudaGetSymbolAddress((void**)&ah,  g_ah);
    cudaGetSymbolAddress((void**)&al,  g_al);
    cudaGetSymbolAddress((void**)&ch,  g_ch);
    cudaGetSymbolAddress((void**)&cl,  g_cl);
    cudaGetSymbolAddress((void**)&bhq, g_bhq);
    cudaGetSymbolAddress((void**)&blq, g_blq);
    cudaGetSymbolAddress((void**)&bho, g_bho);
    cudaGetSymbolAddress((void**)&blo, g_blo);
    cudaGetSymbolAddress((void**)&pmkh, g_pmkh);
    cudaGetSymbolAddress((void**)&pmkl, g_pmkl);
    cudaGetSymbolAddress((void**)&pmvh, g_pmvh);
    cudaGetSymbolAddress((void**)&pmvl, g_pmvl);

    cudaFuncSetAttribute(gemm_mma_k<true>,  cudaFuncAttributeMaxDynamicSharedMemorySize, GSMEM);
    cudaFuncSetAttribute(gemm_mma_k<false>, cudaFuncAttributeMaxDynamicSharedMemorySize, GSMEM);
    cudaFuncSetAttribute(attn_mma_k, cudaFuncAttributeMaxDynamicSharedMemorySize, AT_SMEM);

    // 1) RMSNorm + split
    rmsnorm_split_k<<<NTOK, 256>>>(x, gamma, ah, al);

    // 2) weight prep + pm prep
    tsplit_k<<<dim3(3 * INNER / 32, DD / 32), 256>>>(w_qkv, bhq, blq, DD, 3 * INNER);
    tsplit_k<<<dim3(DD / 32, INNER / 32), 256>>>(w_out, bho, blo, INNER, DD);
    pmsplit_k<<<(HH * PP * DH + 255) / 256, 256>>>(pm_k, pm_v, pmkh, pmkl, pmvh, pmvl);

    // 3) QKV projection -> split bf16 output
    gemm_mma_k<true><<<dim3(3 * INNER / 128, NTOK / 128), 256, GSMEM>>>(
        ah, al, bhq, blq, nullptr, qh, ql, NTOK, 3 * INNER, DD);

    // 4) attention on tensor cores
    attn_mma_k<<<dim3(SEGLEN / 128, NWIN * HH, BB), 256, AT_SMEM>>>(
        qh, ql, pmkh, pmkl, pmvh, pmvl, ch, cl);

    // 5) output projection -> fp32
    gemm_mma_k<false><<<dim3(DD / 128, NTOK / 128), 256, GSMEM>>>(
        ch, cl, bho, blo, out, nullptr, nullptr, NTOK, DD, INNER);
}